// round 5
// baseline (speedup 1.0000x reference)
#include <cuda_runtime.h>
#include <math.h>

#define DM   512
#define LSEQ 256
#define BB   2
#define HH   8
#define DK   64
#define BH   16
#define BL   512
#define NEG_BIG -1.0e30f
#define POS_BIG  1.0e30f

typedef unsigned long long ull;

// ---------------- scratch (device globals; no allocations allowed) -----------
__device__ float g_pp[3 * 8 * BL * DM];    // projection split-K partials (splitK=8)
__device__ float g_op[16 * BL * DM];       // output GEMM split-K partials (splitK=16)
__device__ float g_Q[BH * LSEQ * DK];
__device__ float g_K[BH * LSEQ * DK];
__device__ float g_V[BH * LSEQ * DK];
__device__ float g_ctx[BL * DM];

// ---------------- packed f32x2 helpers (GEMM only) ----------------------------
__device__ __forceinline__ ull pk2(float lo, float hi) {
    ull r;
    asm("mov.b64 %0, {%1, %2};" : "=l"(r) : "f"(lo), "f"(hi));
    return r;
}
__device__ __forceinline__ void upk2(ull v, float& lo, float& hi) {
    asm("mov.b64 {%0, %1}, %2;" : "=f"(lo), "=f"(hi) : "l"(v));
}
__device__ __forceinline__ void fma2(ull& acc, ull a, ull b) {
    asm("fma.rn.f32x2 %0, %1, %2, %0;" : "+l"(acc) : "l"(a), "l"(b));
}

// ---------------- split-K GEMM, double-buffered -------------------------------
// 128m x 64n tile, 256 threads, 8x4 outs/thread (4 packed m-pairs x 4 n), FFMA2.
// mode 0: proj (3 gemms, X=x,     P=g_pp, splitK=8,  klen=64) grid (8,4,24)
// mode 1: out  (1 gemm,  X=g_ctx, P=g_op, splitK=16, klen=32) grid (8,4,16)
__global__ __launch_bounds__(256, 3) void k_gemm(const float* __restrict__ Xin,
                                                 const float* __restrict__ W0,
                                                 const float* __restrict__ W1,
                                                 const float* __restrict__ W2,
                                                 int mode)
{
    __shared__ float As[2][16][130];
    __shared__ ull   Bsd[2][16][65];

    int gemm, zk, nc, k0;
    const float* X;
    float* P;
    if (mode == 0) {
        gemm = blockIdx.z >> 3; zk = blockIdx.z & 7; nc = 4; k0 = zk * 64;
        X = Xin; P = g_pp + (gemm * 8 + zk) * (BL * DM);
    } else {
        gemm = 0; zk = blockIdx.z; nc = 2; k0 = zk * 32;
        X = g_ctx; P = g_op + zk * (BL * DM);
    }
    const float* W = (gemm == 0) ? W0 : ((gemm == 1) ? W1 : W2);

    const int bm = blockIdx.y, bn = blockIdx.x;
    const int tid = threadIdx.x;
    const int tm = tid >> 4;            // 0..15
    const int tn = tid & 15;            // 0..15
    const int lr = tid >> 2;            // A load row base
    const int lk = (tid & 3) * 4;       // A load k-offset
    const int nr = tid & 63;            // B load row
    const int bq = (tid >> 6) * 4;      // B load k-offset

    ull acc[4][4];
#pragma unroll
    for (int p = 0; p < 4; p++)
#pragma unroll
        for (int j = 0; j < 4; j++) acc[p][j] = 0ULL;

    const float* Abase0 = &X[(bm * 128 + lr) * DM + k0 + lk];
    const float* Abase1 = &X[(bm * 128 + lr + 64) * DM + k0 + lk];
    const float* Bbase  = &W[(bn * 64 + nr) * DM + k0 + bq];

    // preload chunk 0
    float4 xa0 = *(const float4*)Abase0;
    float4 xa1 = *(const float4*)Abase1;
    float4 wb  = *(const float4*)Bbase;
    {
        As[0][lk + 0][lr] = xa0.x; As[0][lk + 1][lr] = xa0.y;
        As[0][lk + 2][lr] = xa0.z; As[0][lk + 3][lr] = xa0.w;
        As[0][lk + 0][lr + 64] = xa1.x; As[0][lk + 1][lr + 64] = xa1.y;
        As[0][lk + 2][lr + 64] = xa1.z; As[0][lk + 3][lr + 64] = xa1.w;
        Bsd[0][bq + 0][nr] = pk2(wb.x, wb.x);
        Bsd[0][bq + 1][nr] = pk2(wb.y, wb.y);
        Bsd[0][bq + 2][nr] = pk2(wb.z, wb.z);
        Bsd[0][bq + 3][nr] = pk2(wb.w, wb.w);
    }
    __syncthreads();

    for (int c = 0; c < nc; c++) {
        const int cur = c & 1, nxt = cur ^ 1;
        if (c + 1 < nc) {
            xa0 = *(const float4*)(Abase0 + (c + 1) * 16);
            xa1 = *(const float4*)(Abase1 + (c + 1) * 16);
            wb  = *(const float4*)(Bbase + (c + 1) * 16);
        }
#pragma unroll
        for (int kk = 0; kk < 16; kk++) {
            ull a[4], b[4];
#pragma unroll
            for (int p = 0; p < 4; p++) a[p] = *(const ull*)&As[cur][kk][tm * 8 + 2 * p];
#pragma unroll
            for (int j = 0; j < 4; j++) b[j] = Bsd[cur][kk][tn + j * 16];
#pragma unroll
            for (int p = 0; p < 4; p++)
#pragma unroll
                for (int j = 0; j < 4; j++) fma2(acc[p][j], a[p], b[j]);
        }
        if (c + 1 < nc) {
            As[nxt][lk + 0][lr] = xa0.x; As[nxt][lk + 1][lr] = xa0.y;
            As[nxt][lk + 2][lr] = xa0.z; As[nxt][lk + 3][lr] = xa0.w;
            As[nxt][lk + 0][lr + 64] = xa1.x; As[nxt][lk + 1][lr + 64] = xa1.y;
            As[nxt][lk + 2][lr + 64] = xa1.z; As[nxt][lk + 3][lr + 64] = xa1.w;
            Bsd[nxt][bq + 0][nr] = pk2(wb.x, wb.x);
            Bsd[nxt][bq + 1][nr] = pk2(wb.y, wb.y);
            Bsd[nxt][bq + 2][nr] = pk2(wb.z, wb.z);
            Bsd[nxt][bq + 3][nr] = pk2(wb.w, wb.w);
            __syncthreads();
        }
    }

#pragma unroll
    for (int p = 0; p < 4; p++) {
        const int row = bm * 128 + tm * 8 + 2 * p;
#pragma unroll
        for (int j = 0; j < 4; j++) {
            const int col = bn * 64 + tn + j * 16;
            float lo, hi;
            upk2(acc[p][j], lo, hi);
            P[row * DM + col] = lo;
            P[(row + 1) * DM + col] = hi;
        }
    }
}

// ---------------- tropical linear + split-K reduce + activation ---------------
__global__ __launch_bounds__(256) void k_trop(const float* __restrict__ Wqt,
                                              const float* __restrict__ Wkt,
                                              const float* __restrict__ Wvt,
                                              const float* __restrict__ lam)
{
    __shared__ float Wts[64][65];   // transposed: Wts[i][o]
    __shared__ float ar[16][65];

    const int gemm = blockIdx.z;
    const float* Wt = (gemm == 0) ? Wqt : ((gemm == 1) ? Wkt : Wvt);
    float* out = (gemm == 0) ? g_Q : ((gemm == 1) ? g_K : g_V);
    const int bh = blockIdx.y;
    const int b = bh >> 3, h = bh & 7;
    const int l0 = blockIdx.x * 16;
    const int tid = threadIdx.x;

    for (int idx = tid; idx < 64 * 64; idx += 256) {
        const int o = idx >> 6, i = idx & 63;
        Wts[i][o] = Wt[idx];
    }
    for (int idx = tid; idx < 16 * 64; idx += 256) {
        const int r = idx >> 6, i = idx & 63;
        const int gidx = (b * LSEQ + l0 + r) * DM + h * DK + i;
        const float* p = g_pp + gemm * 8 * (BL * DM) + gidx;
        float s = 0.0f;
#pragma unroll
        for (int z = 0; z < 8; z++) s += p[z * (BL * DM)];
        ar[r][i] = log1pf(fmaxf(s, 0.0f)) - lam[h * DK + i];
    }
    __syncthreads();

    const int o = tid & 63, rg = tid >> 6;
    float m[4] = {NEG_BIG, NEG_BIG, NEG_BIG, NEG_BIG};
#pragma unroll 8
    for (int i = 0; i < 64; i++) {
        const float wv = Wts[i][o];
#pragma unroll
        for (int rr = 0; rr < 4; rr++)
            m[rr] = fmaxf(m[rr], ar[rg * 4 + rr][i] + wv);
    }
#pragma unroll
    for (int rr = 0; rr < 4; rr++)
        out[(bh * LSEQ + l0 + rg * 4 + rr) * DK + o] = m[rr];
}

// ---------------- fused tropical attention ------------------------------------
// i-tile = 8 rows, grid (32, 16) = 512 blocks, 256 threads, ~50 regs.
// scores[bh,i,j] = min_d(q_i-k_j) - max_d(q_i-k_j)
// ctx = expm1( max_j(scores + v[j,d]) ), merged to (B,L,DM)
__global__ __launch_bounds__(256, 4) void k_attn(float* __restrict__ scores)
{
    __shared__ float Qs[8][68];
    __shared__ float Ks[64][68];
    __shared__ float Vs[64][68];
    __shared__ float Ss[64][9];

    const int bh = blockIdx.y;
    const int it = blockIdx.x;        // 0..31
    const int i0 = it * 8;
    const int b = bh >> 3, h = bh & 7;
    const int tid = threadIdx.x;
    const int lane = tid & 31;
    const int w  = tid >> 5;          // warp 0..7 = phase-B i row
    const int ii = tid & 7;           // phase-A i
    const int jg = tid >> 3;          // phase-A j-group (0..31), 2 j each

    // load Q tile (8 x 64)
    if (tid < 128) {
        const int r = tid >> 4, dq = (tid & 15) * 4;
        *(float4*)&Qs[r][dq] = *(const float4*)&g_Q[(bh * LSEQ + i0 + r) * DK + dq];
    }

    float accE0 = NEG_BIG, accE1 = NEG_BIG;   // even j
    float accO0 = NEG_BIG, accO1 = NEG_BIG;   // odd j

    for (int c = 0; c < 4; c++) {
        const float4* Kp = (const float4*)(g_K + (bh * LSEQ + c * 64) * DK);
        const float4* Vp = (const float4*)(g_V + (bh * LSEQ + c * 64) * DK);
        for (int idx = tid; idx < 1024; idx += 256) {
            const int j = idx >> 4, dq = (idx & 15) * 4;
            *(float4*)&Ks[j][dq] = Kp[idx];
            *(float4*)&Vs[j][dq] = Vp[idx];
        }
        __syncthreads();

        // ---- phase A: scores for 2 j per thread ----
        {
            const int j0 = jg * 2;
            float mxa[2] = {NEG_BIG, NEG_BIG}, mxb[2] = {NEG_BIG, NEG_BIG};
            float mna[2] = {POS_BIG, POS_BIG}, mnb[2] = {POS_BIG, POS_BIG};
#pragma unroll
            for (int t = 0; t < 16; t++) {
                const float4 q4 = *(const float4*)&Qs[ii][t * 4];
#pragma unroll
                for (int jj = 0; jj < 2; jj++) {
                    const float4 k4 = *(const float4*)&Ks[j0 + jj][t * 4];
                    const float d0 = q4.x - k4.x;
                    const float d1 = q4.y - k4.y;
                    const float d2 = q4.z - k4.z;
                    const float d3 = q4.w - k4.w;
                    mxa[jj] = fmaxf(mxa[jj], d0); mna[jj] = fminf(mna[jj], d0);
                    mxb[jj] = fmaxf(mxb[jj], d1); mnb[jj] = fminf(mnb[jj], d1);
                    mxa[jj] = fmaxf(mxa[jj], d2); mna[jj] = fminf(mna[jj], d2);
                    mxb[jj] = fmaxf(mxb[jj], d3); mnb[jj] = fminf(mnb[jj], d3);
                }
            }
#pragma unroll
            for (int jj = 0; jj < 2; jj++) {
                const float sc = fminf(mna[jj], mnb[jj]) - fmaxf(mxa[jj], mxb[jj]);
                Ss[j0 + jj][ii] = sc;
                scores[(bh * LSEQ + i0 + ii) * LSEQ + c * 64 + j0 + jj] = sc;
            }
        }
        __syncthreads();

        // ---- phase B: context (warp = i row, d across lanes, j serial) ----
#pragma unroll 4
        for (int j = 0; j < 64; j += 2) {
            const float sE = Ss[j][w];         // broadcast
            const float sO = Ss[j + 1][w];
            const float2 vE = *(const float2*)&Vs[j][lane * 2];
            const float2 vO = *(const float2*)&Vs[j + 1][lane * 2];
            accE0 = fmaxf(accE0, sE + vE.x);
            accE1 = fmaxf(accE1, sE + vE.y);
            accO0 = fmaxf(accO0, sO + vO.x);
            accO1 = fmaxf(accO1, sO + vO.y);
        }
        __syncthreads();
    }

    // merge + write ctx
    {
        const int l = i0 + w;
        float2 v;
        v.x = expm1f(fmaxf(accE0, accO0));
        v.y = expm1f(fmaxf(accE1, accO1));
        *(float2*)&g_ctx[(b * LSEQ + l) * DM + h * DK + lane * 2] = v;
    }
}

// ---------------- split-K reduce for the output GEMM --------------------------
__global__ __launch_bounds__(256) void k_reduce(float* __restrict__ out)
{
    const int idx = blockIdx.x * 256 + threadIdx.x;   // float4 index, 65536 total
    const float4* p = (const float4*)g_op;
    float4 s = p[idx];
#pragma unroll
    for (int z = 1; z < 16; z++) {
        const float4 t = p[z * 65536 + idx];
        s.x += t.x; s.y += t.y; s.z += t.z; s.w += t.w;
    }
    ((float4*)out)[idx] = s;
}

// ---------------- launch ------------------------------------------------------
extern "C" void kernel_launch(void* const* d_in, const int* in_sizes, int n_in,
                              void* d_out, int out_size)
{
    const float* x   = (const float*)d_in[0];
    const float* Wq  = (const float*)d_in[1];
    const float* Wk  = (const float*)d_in[2];
    const float* Wv  = (const float*)d_in[3];
    const float* Wo  = (const float*)d_in[4];
    const float* lam = (const float*)d_in[5];
    const float* Wqt = (const float*)d_in[6];
    const float* Wkt = (const float*)d_in[7];
    const float* Wvt = (const float*)d_in[8];
    float* out = (float*)d_out;
    float* scores = out + BL * DM;   // (output, attn_scores) flattened in order

    k_gemm<<<dim3(8, 4, 24), 256>>>(x, Wq, Wk, Wv, 0);        // projections, splitK=8
    k_trop<<<dim3(16, 16, 3), 256>>>(Wqt, Wkt, Wvt, lam);     // reduce+activate+tropical
    k_attn<<<dim3(32, 16), 256>>>(scores);                    // fused scores+context
    k_gemm<<<dim3(8, 4, 16), 256>>>(nullptr, Wo, nullptr, nullptr, 1); // out GEMM, splitK=16
    k_reduce<<<256, 256>>>(out);                              // splitK reduce
}

// round 6
// speedup vs baseline: 1.0718x; 1.0718x over previous
#include <cuda_runtime.h>
#include <math.h>

#define DM   512
#define LSEQ 256
#define BB   2
#define HH   8
#define DK   64
#define BH   16
#define BL   512
#define NEG_BIG -1.0e30f
#define POS_BIG  1.0e30f
#define CHK  8

typedef unsigned long long ull;

// ---------------- scratch (device globals; no allocations allowed) -----------
__device__ float g_pp[3 * 8 * BL * DM];   // projection split-K partials (splitK=8)
__device__ float g_op[8 * BL * DM];       // output GEMM split-K partials (splitK=8)
__device__ float g_Q[BH * LSEQ * DK];
__device__ float g_K[BH * LSEQ * DK];
__device__ float g_V[BH * LSEQ * DK];
__device__ float g_ctx[BL * DM];

// ---------------- packed f32x2 helpers (GEMM only) ----------------------------
__device__ __forceinline__ ull pk2(float lo, float hi) {
    ull r;
    asm("mov.b64 %0, {%1, %2};" : "=l"(r) : "f"(lo), "f"(hi));
    return r;
}
__device__ __forceinline__ void upk2(ull v, float& lo, float& hi) {
    asm("mov.b64 {%0, %1}, %2;" : "=f"(lo), "=f"(hi) : "l"(v));
}
__device__ __forceinline__ void fma2(ull& acc, ull a, ull b) {
    asm("fma.rn.f32x2 %0, %1, %2, %0;" : "+l"(acc) : "l"(a), "l"(b));
}

// ---------------- split-K GEMM: 128m x 128n tile, 8x8 per thread, FFMA2 ------
// 256 threads, acc = 4 packed m-pairs x 8 n. Double-buffered, chunk = 8 k.
// mode 0: proj (3 gemms, X=x,     P=g_pp, splitK=8, klen=64) grid (4,4,24)
// mode 1: out  (1 gemm,  X=g_ctx, P=g_op, splitK=8, klen=64) grid (4,4,8)
__global__ __launch_bounds__(256, 2) void k_gemm(const float* __restrict__ Xin,
                                                 const float* __restrict__ W0,
                                                 const float* __restrict__ W1,
                                                 const float* __restrict__ W2,
                                                 int mode)
{
    __shared__ float As[2][CHK][130];    // [kk][m-row]
    __shared__ ull   Bsd[2][CHK][130];   // [kk][n-row] pre-duplicated {b,b}

    int gemm, zk;
    const float* X;
    float* P;
    if (mode == 0) {
        gemm = blockIdx.z >> 3; zk = blockIdx.z & 7;
        X = Xin; P = g_pp + (gemm * 8 + zk) * (BL * DM);
    } else {
        gemm = 0; zk = blockIdx.z;
        X = g_ctx; P = g_op + zk * (BL * DM);
    }
    const float* W = (gemm == 0) ? W0 : ((gemm == 1) ? W1 : W2);
    const int k0 = zk * 64;
    const int nc = 64 / CHK;             // 8 chunks

    const int bm = blockIdx.y, bn = blockIdx.x;
    const int tid = threadIdx.x;
    const int tm = tid >> 4;             // 0..15 -> m rows tm*8..tm*8+7
    const int tn = tid & 15;             // 0..15 -> n cols tn + j*16
    const int lr = tid >> 1;             // 0..127 load row (A and B)
    const int lq = (tid & 1) * 4;        // k-offset (float4) within chunk

    ull acc[4][8];
#pragma unroll
    for (int p = 0; p < 4; p++)
#pragma unroll
        for (int j = 0; j < 8; j++) acc[p][j] = 0ULL;

    const float* Ap = &X[(bm * 128 + lr) * DM + k0 + lq];
    const float* Bp = &W[(bn * 128 + lr) * DM + k0 + lq];

    // preload chunk 0
    float4 xa = *(const float4*)Ap;
    float4 wb = *(const float4*)Bp;
    As[0][lq + 0][lr] = xa.x; As[0][lq + 1][lr] = xa.y;
    As[0][lq + 2][lr] = xa.z; As[0][lq + 3][lr] = xa.w;
    Bsd[0][lq + 0][lr] = pk2(wb.x, wb.x);
    Bsd[0][lq + 1][lr] = pk2(wb.y, wb.y);
    Bsd[0][lq + 2][lr] = pk2(wb.z, wb.z);
    Bsd[0][lq + 3][lr] = pk2(wb.w, wb.w);
    __syncthreads();

    for (int c = 0; c < nc; c++) {
        const int cur = c & 1, nxt = cur ^ 1;
        if (c + 1 < nc) {
            xa = *(const float4*)(Ap + (c + 1) * CHK);
            wb = *(const float4*)(Bp + (c + 1) * CHK);
        }
#pragma unroll
        for (int kk = 0; kk < CHK; kk++) {
            ull a[4], b[8];
#pragma unroll
            for (int p = 0; p < 4; p++) a[p] = *(const ull*)&As[cur][kk][tm * 8 + 2 * p];
#pragma unroll
            for (int j = 0; j < 8; j++) b[j] = Bsd[cur][kk][tn + j * 16];
#pragma unroll
            for (int p = 0; p < 4; p++)
#pragma unroll
                for (int j = 0; j < 8; j++) fma2(acc[p][j], a[p], b[j]);
        }
        if (c + 1 < nc) {
            As[nxt][lq + 0][lr] = xa.x; As[nxt][lq + 1][lr] = xa.y;
            As[nxt][lq + 2][lr] = xa.z; As[nxt][lq + 3][lr] = xa.w;
            Bsd[nxt][lq + 0][lr] = pk2(wb.x, wb.x);
            Bsd[nxt][lq + 1][lr] = pk2(wb.y, wb.y);
            Bsd[nxt][lq + 2][lr] = pk2(wb.z, wb.z);
            Bsd[nxt][lq + 3][lr] = pk2(wb.w, wb.w);
            __syncthreads();
        }
    }

#pragma unroll
    for (int p = 0; p < 4; p++) {
        const int row = bm * 128 + tm * 8 + 2 * p;
#pragma unroll
        for (int j = 0; j < 8; j++) {
            const int col = bn * 128 + tn + j * 16;
            float lo, hi;
            upk2(acc[p][j], lo, hi);
            P[row * DM + col] = lo;
            P[(row + 1) * DM + col] = hi;
        }
    }
}

// ---------------- tropical linear + split-K reduce + activation ---------------
__global__ __launch_bounds__(256) void k_trop(const float* __restrict__ Wqt,
                                              const float* __restrict__ Wkt,
                                              const float* __restrict__ Wvt,
                                              const float* __restrict__ lam)
{
    __shared__ float Wts[64][65];   // transposed: Wts[i][o]
    __shared__ float ar[16][65];

    const int gemm = blockIdx.z;
    const float* Wt = (gemm == 0) ? Wqt : ((gemm == 1) ? Wkt : Wvt);
    float* out = (gemm == 0) ? g_Q : ((gemm == 1) ? g_K : g_V);
    const int bh = blockIdx.y;
    const int b = bh >> 3, h = bh & 7;
    const int l0 = blockIdx.x * 16;
    const int tid = threadIdx.x;

    for (int idx = tid; idx < 64 * 64; idx += 256) {
        const int o = idx >> 6, i = idx & 63;
        Wts[i][o] = Wt[idx];
    }
    for (int idx = tid; idx < 16 * 64; idx += 256) {
        const int r = idx >> 6, i = idx & 63;
        const int gidx = (b * LSEQ + l0 + r) * DM + h * DK + i;
        const float* p = g_pp + gemm * 8 * (BL * DM) + gidx;
        float s = 0.0f;
#pragma unroll
        for (int z = 0; z < 8; z++) s += p[z * (BL * DM)];
        ar[r][i] = log1pf(fmaxf(s, 0.0f)) - lam[h * DK + i];
    }
    __syncthreads();

    const int o = tid & 63, rg = tid >> 6;
    float m[4] = {NEG_BIG, NEG_BIG, NEG_BIG, NEG_BIG};
#pragma unroll 8
    for (int i = 0; i < 64; i++) {
        const float wv = Wts[i][o];
#pragma unroll
        for (int rr = 0; rr < 4; rr++)
            m[rr] = fmaxf(m[rr], ar[rg * 4 + rr][i] + wv);
    }
#pragma unroll
    for (int rr = 0; rr < 4; rr++)
        out[(bh * LSEQ + l0 + rg * 4 + rr) * DK + o] = m[rr];
}

// ---------------- fused tropical attention ------------------------------------
// i-tile = 8 rows, grid (32, 16) = 512 blocks, 256 threads.
__global__ __launch_bounds__(256, 4) void k_attn(float* __restrict__ scores)
{
    __shared__ float Qs[8][68];
    __shared__ float Ks[64][68];
    __shared__ float Vs[64][68];
    __shared__ float Ss[64][9];

    const int bh = blockIdx.y;
    const int it = blockIdx.x;        // 0..31
    const int i0 = it * 8;
    const int b = bh >> 3, h = bh & 7;
    const int tid = threadIdx.x;
    const int lane = tid & 31;
    const int w  = tid >> 5;          // warp 0..7 = phase-B i row
    const int ii = tid & 7;           // phase-A i
    const int jg = tid >> 3;          // phase-A j-group (0..31), 2 j each

    if (tid < 128) {
        const int r = tid >> 4, dq = (tid & 15) * 4;
        *(float4*)&Qs[r][dq] = *(const float4*)&g_Q[(bh * LSEQ + i0 + r) * DK + dq];
    }

    float accE0 = NEG_BIG, accE1 = NEG_BIG;
    float accO0 = NEG_BIG, accO1 = NEG_BIG;

    for (int c = 0; c < 4; c++) {
        const float4* Kp = (const float4*)(g_K + (bh * LSEQ + c * 64) * DK);
        const float4* Vp = (const float4*)(g_V + (bh * LSEQ + c * 64) * DK);
        for (int idx = tid; idx < 1024; idx += 256) {
            const int j = idx >> 4, dq = (idx & 15) * 4;
            *(float4*)&Ks[j][dq] = Kp[idx];
            *(float4*)&Vs[j][dq] = Vp[idx];
        }
        __syncthreads();

        // ---- phase A: scores for 2 j per thread ----
        {
            const int j0 = jg * 2;
            float mxa[2] = {NEG_BIG, NEG_BIG}, mxb[2] = {NEG_BIG, NEG_BIG};
            float mna[2] = {POS_BIG, POS_BIG}, mnb[2] = {POS_BIG, POS_BIG};
#pragma unroll
            for (int t = 0; t < 16; t++) {
                const float4 q4 = *(const float4*)&Qs[ii][t * 4];
#pragma unroll
                for (int jj = 0; jj < 2; jj++) {
                    const float4 k4 = *(const float4*)&Ks[j0 + jj][t * 4];
                    const float d0 = q4.x - k4.x;
                    const float d1 = q4.y - k4.y;
                    const float d2 = q4.z - k4.z;
                    const float d3 = q4.w - k4.w;
                    mxa[jj] = fmaxf(mxa[jj], d0); mna[jj] = fminf(mna[jj], d0);
                    mxb[jj] = fmaxf(mxb[jj], d1); mnb[jj] = fminf(mnb[jj], d1);
                    mxa[jj] = fmaxf(mxa[jj], d2); mna[jj] = fminf(mna[jj], d2);
                    mxb[jj] = fmaxf(mxb[jj], d3); mnb[jj] = fminf(mnb[jj], d3);
                }
            }
#pragma unroll
            for (int jj = 0; jj < 2; jj++) {
                const float sc = fminf(mna[jj], mnb[jj]) - fmaxf(mxa[jj], mxb[jj]);
                Ss[j0 + jj][ii] = sc;
                scores[(bh * LSEQ + i0 + ii) * LSEQ + c * 64 + j0 + jj] = sc;
            }
        }
        __syncthreads();

        // ---- phase B: context (warp = i row, d across lanes, j serial) ----
#pragma unroll 4
        for (int j = 0; j < 64; j += 2) {
            const float sE = Ss[j][w];
            const float sO = Ss[j + 1][w];
            const float2 vE = *(const float2*)&Vs[j][lane * 2];
            const float2 vO = *(const float2*)&Vs[j + 1][lane * 2];
            accE0 = fmaxf(accE0, sE + vE.x);
            accE1 = fmaxf(accE1, sE + vE.y);
            accO0 = fmaxf(accO0, sO + vO.x);
            accO1 = fmaxf(accO1, sO + vO.y);
        }
        __syncthreads();
    }

    {
        const int l = i0 + w;
        float2 v;
        v.x = expm1f(fmaxf(accE0, accO0));
        v.y = expm1f(fmaxf(accE1, accO1));
        *(float2*)&g_ctx[(b * LSEQ + l) * DM + h * DK + lane * 2] = v;
    }
}

// ---------------- split-K reduce for the output GEMM --------------------------
__global__ __launch_bounds__(256) void k_reduce(float* __restrict__ out)
{
    const int idx = blockIdx.x * 256 + threadIdx.x;   // float4 index, 65536 total
    const float4* p = (const float4*)g_op;
    float4 s = p[idx];
#pragma unroll
    for (int z = 1; z < 8; z++) {
        const float4 t = p[z * 65536 + idx];
        s.x += t.x; s.y += t.y; s.z += t.z; s.w += t.w;
    }
    ((float4*)out)[idx] = s;
}

// ---------------- launch ------------------------------------------------------
extern "C" void kernel_launch(void* const* d_in, const int* in_sizes, int n_in,
                              void* d_out, int out_size)
{
    const float* x   = (const float*)d_in[0];
    const float* Wq  = (const float*)d_in[1];
    const float* Wk  = (const float*)d_in[2];
    const float* Wv  = (const float*)d_in[3];
    const float* Wo  = (const float*)d_in[4];
    const float* lam = (const float*)d_in[5];
    const float* Wqt = (const float*)d_in[6];
    const float* Wkt = (const float*)d_in[7];
    const float* Wvt = (const float*)d_in[8];
    float* out = (float*)d_out;
    float* scores = out + BL * DM;   // (output, attn_scores) flattened in order

    k_gemm<<<dim3(4, 4, 24), 256>>>(x, Wq, Wk, Wv, 0);        // projections, splitK=8
    k_trop<<<dim3(16, 16, 3), 256>>>(Wqt, Wkt, Wvt, lam);     // reduce+activate+tropical
    k_attn<<<dim3(32, 16), 256>>>(scores);                    // fused scores+context
    k_gemm<<<dim3(4, 4, 8), 256>>>(nullptr, Wo, nullptr, nullptr, 1);  // out GEMM, splitK=8
    k_reduce<<<256, 256>>>(out);                              // splitK reduce
}